// round 16
// baseline (speedup 1.0000x reference)
#include <cuda_runtime.h>
#include <cuda_fp16.h>
#include <cstdint>

// ---------------- problem constants ----------------
#define NB     65536
#define GS     7
#define INH    5
#define GH     144
#define LINH   128
#define GPC    4              // graphs per CTA (padded to 8 rows each)
#define NCTA   (NB/GPC)       // 16384
#define NTHR   128            // 4 warps: (nh 0..1) x (sl 0..1)
#define KT     9              // 144/16 k-tiles
#define NT     18             // 144/8 n-tiles
#define NTP    9              // nt-pairs
#define HS2    296            // sH row stride (floats); 296 % 32 == 8 -> conflict-free stores
#define ADJD   112            // duplicated adjacency stride per graph: 7 rows x 8 x 2
#define BSLOT  (KT*NT*256)    // 41472 bytes per weight slot

typedef unsigned long long ull;

// ---------------- device scratch ----------------
__device__ unsigned char g_B[4*BSLOT];   // frag-packed fp16 weights (paired-nt uint4)
__device__ float g_v[GH];                // fused fc vector

// ---------------- helpers ----------------
__device__ __forceinline__ uint32_t pack_h(float a, float b) {
    __half2 t = __floats2half2_rn(a, b);   // a in low half
    return *(uint32_t*)&t;
}
__device__ __forceinline__ void fma2(ull& d, ull a, ull b) {
    asm("fma.rn.f32x2 %0, %1, %2, %0;" : "+l"(d) : "l"(a), "l"(b));
}
__device__ __forceinline__ ull pack2(float a, float b) {
    ull r; asm("mov.b64 %0, {%1, %2};" : "=l"(r) : "f"(a), "f"(b)); return r;
}
__device__ __forceinline__ void unpack2(float& a, float& b, ull v) {
    asm("mov.b64 {%0, %1}, %2;" : "=f"(a), "=f"(b) : "l"(v));
}
__device__ __forceinline__ void mma_f16(float* c, uint32_t a0, uint32_t a1,
                                        uint32_t a2, uint32_t a3,
                                        uint32_t b0, uint32_t b1) {
    asm volatile(
        "mma.sync.aligned.m16n8k16.row.col.f32.f16.f16.f32 "
        "{%0,%1,%2,%3}, {%4,%5,%6,%7}, {%8,%9}, {%0,%1,%2,%3};"
        : "+f"(c[0]), "+f"(c[1]), "+f"(c[2]), "+f"(c[3])
        : "r"(a0), "r"(a1), "r"(a2), "r"(a3), "r"(b0), "r"(b1));
}

// ---------------- shared memory ----------------
struct SM {
    union {
        uint4 sX[2*KT*32];      // 9216 B: frag-packed fp16 X (2 mtiles)
        struct { float ops[GPC*35]; float w0[2*720]; } l0;
    } u;
    float h[32*HS2];            // 37888 B: 32 rows x [h1(144) | h2(144)] fp32
    float adjn[GPC*ADJD];       // duplicated [g][7][8x2]: (a,a) pairs, col 7 = 0
    float adji[GPC*ADJD];
    float adjraw[GPC*49];
    float v[GH];
    float gsum[GPC];
};
#define SMEMB ((int)sizeof(SM))   // ~52.4 KB -> 4 CTAs/SM

// ================= prep kernel: blocks 0-3 pack B, block 4 builds v ===========
// slot order: 0=w1_1 1=w2_1 2=w1_2 3=w2_2.
// B layout: block (kt, ntp) of 512 B; lane l holds [nt=2ntp uint2][nt=2ntp+1 uint2]
__global__ void k_prep(const float* __restrict__ wa, const float* __restrict__ wb,
                       const float* __restrict__ wc, const float* __restrict__ wd,
                       const float* __restrict__ fc1, const float* __restrict__ fc2) {
    if (blockIdx.x == 4) {
        const int k = threadIdx.x;
        if (k < GH) {
            float s = 0.f;
            for (int j = 0; j < LINH; j++) s = fmaf(fc2[j], fc1[j*GH + k], s);
            g_v[k] = s;
        }
        return;
    }
    const float* W = blockIdx.x == 0 ? wa : blockIdx.x == 1 ? wb
                   : blockIdx.x == 2 ? wc : wd;
    unsigned char* out = g_B + (size_t)blockIdx.x * BSLOT;
    for (int f = threadIdx.x; f < KT*NT*32; f += 256) {
        const int kt = f / (NT*32);
        const int nt = (f / 32) % NT;
        const int l  = f & 31;
        const int n  = nt*8 + (l >> 2);
        const int kb = kt*16 + (l & 3)*2;
        uint2 v;
        v.x = pack_h(W[(kb+0)*GH + n], W[(kb+1)*GH + n]);
        v.y = pack_h(W[(kb+8)*GH + n], W[(kb+9)*GH + n]);
        *(uint2*)(out + (size_t)(kt*NTP + (nt >> 1))*512 + l*16 + (nt & 1)*8) = v;
    }
}

// ================= per-graph adjacency prep (duplicated-pair output) ==========
__device__ void prep_graph(SM* s, int g) {
    float a[49];
#pragma unroll
    for (int i = 0; i < 49; i++) a[i] = s->adjraw[g*49 + i];
#pragma unroll
    for (int i = 0; i < 7; i++) {
        a[i*7 + i] += 1.0f;
        float rs = 0.f;
#pragma unroll
        for (int j = 0; j < 7; j++) rs += a[i*7 + j];
        const float inv = 1.0f / rs;
#pragma unroll
        for (int j = 0; j < 7; j++) a[i*7 + j] *= inv;
    }
#pragma unroll
    for (int i = 0; i < 7; i++) {
        float rs = 0.f;
#pragma unroll
        for (int j = 0; j < 7; j++) rs += a[i*7 + j];
        const float inv = 1.0f / rs;
#pragma unroll
        for (int j = 0; j < 7; j++) {
            const float vv = a[i*7 + j] * inv;
            s->adjn[g*ADJD + i*16 + 2*j]     = vv;
            s->adjn[g*ADJD + i*16 + 2*j + 1] = vv;
        }
        s->adjn[g*ADJD + i*16 + 14] = 0.f;
        s->adjn[g*ADJD + i*16 + 15] = 0.f;
    }
#pragma unroll
    for (int i = 0; i < 7; i++) {
        float cs = 0.f;
#pragma unroll
        for (int r = 0; r < 7; r++) cs += a[r*7 + i];
        const float inv = 1.0f / cs;
#pragma unroll
        for (int j = 0; j < 7; j++) {
            const float vv = a[j*7 + i] * inv;
            s->adji[g*ADJD + i*16 + 2*j]     = vv;
            s->adji[g*ADJD + i*16 + 2*j + 1] = vv;
        }
        s->adji[g*ADJD + i*16 + 14] = 0.f;
        s->adji[g*ADJD + i*16 + 15] = 0.f;
    }
}

// ================= mix: sH -> (sX frags | pooled gsum), FFMA2 inner ===========
template <bool FINAL>
__device__ void mix(SM* s) {
    const int tid = threadIdx.x;
    __syncthreads();   // sH complete; prior sX reads done

    for (int item = tid; item < GPC*36; item += NTHR) {
        const int g  = item / 36;
        const int kq = item - g*36;
        const int k0 = kq*4;

        ull h1x[7], h1z[7], h2x[7], h2z[7];
#pragma unroll
        for (int j = 0; j < 7; j++) {
            const ulonglong2 t1 = *(const ulonglong2*)&s->h[(g*8+j)*HS2 + k0];
            const ulonglong2 t2 = *(const ulonglong2*)&s->h[(g*8+j)*HS2 + GH + k0];
            h1x[j] = t1.x; h1z[j] = t1.y;
            h2x[j] = t2.x; h2z[j] = t2.y;
        }
        const ulonglong2* an = (const ulonglong2*)&s->adjn[g*ADJD];
        const ulonglong2* ai = (const ulonglong2*)&s->adji[g*ADJD];

        const int mt = g >> 1;
        const int kt = kq >> 2;
        const int c20 = (kq & 3)*2;
        uint32_t* X = (uint32_t*)s->u.sX;
        const int base  = (mt*KT + kt)*128;
        const int wsel  = (g & 1) + 2*(c20 >> 2);
        const int lbase = c20 & 3;             // 0 or 2

        float cs0 = 0.f, cs1 = 0.f, cs2 = 0.f, cs3 = 0.f;
#pragma unroll
        for (int i = 0; i < 7; i++) {
            const ulonglong2 wn01 = an[i*4],   wn23 = an[i*4+1];
            const ulonglong2 wn45 = an[i*4+2], wn6p = an[i*4+3];
            const ulonglong2 wi01 = ai[i*4],   wi23 = ai[i*4+1];
            const ulonglong2 wi45 = ai[i*4+2], wi6p = ai[i*4+3];

            ull o1x = 0ull, o1z = 0ull, o2x = 0ull, o2z = 0ull;
            fma2(o1x, wn01.x, h1x[0]); fma2(o1z, wn01.x, h1z[0]);
            fma2(o1x, wn01.y, h1x[1]); fma2(o1z, wn01.y, h1z[1]);
            fma2(o1x, wn23.x, h1x[2]); fma2(o1z, wn23.x, h1z[2]);
            fma2(o1x, wn23.y, h1x[3]); fma2(o1z, wn23.y, h1z[3]);
            fma2(o1x, wn45.x, h1x[4]); fma2(o1z, wn45.x, h1z[4]);
            fma2(o1x, wn45.y, h1x[5]); fma2(o1z, wn45.y, h1z[5]);
            fma2(o1x, wn6p.x, h1x[6]); fma2(o1z, wn6p.x, h1z[6]);
            fma2(o2x, wi01.x, h2x[0]); fma2(o2z, wi01.x, h2z[0]);
            fma2(o2x, wi01.y, h2x[1]); fma2(o2z, wi01.y, h2z[1]);
            fma2(o2x, wi23.x, h2x[2]); fma2(o2z, wi23.x, h2z[2]);
            fma2(o2x, wi23.y, h2x[3]); fma2(o2z, wi23.y, h2z[3]);
            fma2(o2x, wi45.x, h2x[4]); fma2(o2z, wi45.x, h2z[4]);
            fma2(o2x, wi45.y, h2x[5]); fma2(o2z, wi45.y, h2z[5]);
            fma2(o2x, wi6p.x, h2x[6]); fma2(o2z, wi6p.x, h2z[6]);

            float o1a, o1b, o1c, o1d, o2a, o2b, o2c, o2d;
            unpack2(o1a, o1b, o1x); unpack2(o1c, o1d, o1z);
            unpack2(o2a, o2b, o2x); unpack2(o2c, o2d, o2z);
            const float x0 = 0.5f * (fmaxf(o1a, 0.f) + fmaxf(o2a, 0.f));
            const float x1 = 0.5f * (fmaxf(o1b, 0.f) + fmaxf(o2b, 0.f));
            const float x2 = 0.5f * (fmaxf(o1c, 0.f) + fmaxf(o2c, 0.f));
            const float x3 = 0.5f * (fmaxf(o1d, 0.f) + fmaxf(o2d, 0.f));

            if (!FINAL) {
                const int l = i*4 + lbase;
                X[base + l*4 + wsel]     = pack_h(x0, x1);
                X[base + (l+1)*4 + wsel] = pack_h(x2, x3);
            } else {
                cs0 += x0; cs1 += x1; cs2 += x2; cs3 += x3;
            }
        }
        if (FINAL)
            atomicAdd(&s->gsum[g], cs0*s->v[k0] + cs1*s->v[k0+1]
                                 + cs2*s->v[k0+2] + cs3*s->v[k0+3]);
    }
    __syncthreads();   // sX/gsum complete before next phase
}

// ================= GEMM: both mtiles per warp; B uint4 feeds 4 mma ===========
template <int P0, int PN>
__device__ void gemm(SM* s, int sl, int slot) {
    const int lane = threadIdx.x & 31;
    const uint4* __restrict__ Bp = (const uint4*)(g_B + (size_t)slot*BSLOT);
    const uint4* Xv = s->u.sX;

    float acc[2][2*PN][4];
#pragma unroll
    for (int m = 0; m < 2; m++)
#pragma unroll
        for (int t = 0; t < 2*PN; t++)
#pragma unroll
            for (int q = 0; q < 4; q++) acc[m][t][q] = 0.f;

#pragma unroll 1
    for (int kt = 0; kt < KT; kt++) {
        const uint4 a0 = Xv[kt*32 + lane];
        const uint4 a1 = Xv[(KT + kt)*32 + lane];
#pragma unroll
        for (int p = 0; p < PN; p++) {
            const uint4 b = Bp[(kt*NTP + P0 + p)*32 + lane];
            mma_f16(acc[0][2*p],     a0.x, a0.y, a0.z, a0.w, b.x, b.y);
            mma_f16(acc[0][2*p + 1], a0.x, a0.y, a0.z, a0.w, b.z, b.w);
            mma_f16(acc[1][2*p],     a1.x, a1.y, a1.z, a1.w, b.x, b.y);
            mma_f16(acc[1][2*p + 1], a1.x, a1.y, a1.z, a1.w, b.z, b.w);
        }
    }

    const int c0 = sl*GH + (lane & 3)*2;
#pragma unroll
    for (int m = 0; m < 2; m++) {
        const int r0 = m*16 + (lane >> 2);
#pragma unroll
        for (int p = 0; p < PN; p++) {
#pragma unroll
            for (int q = 0; q < 2; q++) {
                const int nt = 2*(P0 + p) + q;
                *(float2*)&s->h[r0*HS2 + c0 + nt*8]     = make_float2(acc[m][2*p+q][0], acc[m][2*p+q][1]);
                *(float2*)&s->h[(r0+8)*HS2 + c0 + nt*8] = make_float2(acc[m][2*p+q][2], acc[m][2*p+q][3]);
            }
        }
    }
}

// ================= the fused kernel ===========================================
__global__ void __launch_bounds__(NTHR, 4)
k_fused(const float* __restrict__ ops, const float* __restrict__ adj,
        const float* __restrict__ nv,
        const float* __restrict__ w1_0, const float* __restrict__ w2_0,
        float* __restrict__ out) {
    extern __shared__ unsigned char smraw[];
    SM* s = (SM*)smraw;
    const int cta = blockIdx.x, tid = threadIdx.x;
    const int warp = tid >> 5, lane = tid & 31;
    const int sl = warp & 1, nh = warp >> 1;

    // ---- cooperative loads ----
    for (int q = tid; q < GPC*35; q += NTHR) s->u.l0.ops[q] = ops[(size_t)cta*GPC*35 + q];
    for (int q = tid; q < 720; q += NTHR) {
        s->u.l0.w0[q]       = w1_0[q];
        s->u.l0.w0[720 + q] = w2_0[q];
    }
    for (int q = tid; q < GH; q += NTHR)     s->v[q] = g_v[q];
    for (int q = tid; q < GPC*49; q += NTHR) s->adjraw[q] = adj[(size_t)cta*GPC*49 + q];
    if (tid < GPC) s->gsum[tid] = 0.f;
    __syncthreads();

    // ---- adjacency prep (one thread per graph) ----
    if (tid < GPC) prep_graph(s, tid);

    // ---- layer 0: h = ops @ W (K=5), FFMA2 inner; warp covers (sl, nh), both mt
    {
        const int r0 = lane >> 2;          // 0..7 (7 = pad row)
        const float* W = &s->u.l0.w0[sl*720];
        const int cb = sl*GH + (lane & 3)*2;
#pragma unroll
        for (int m = 0; m < 2; m++) {
            const int g0 = 2*m, g1 = 2*m + 1;
            ull o0d[INH], o1d[INH];
#pragma unroll
            for (int t = 0; t < INH; t++) {
                const float a0 = (r0 < 7) ? s->u.l0.ops[g0*35 + r0*5 + t] : 0.f;
                const float a1 = (r0 < 7) ? s->u.l0.ops[g1*35 + r0*5 + t] : 0.f;
                o0d[t] = pack2(a0, a0);
                o1d[t] = pack2(a1, a1);
            }
            const int rr = m*16 + r0;
#pragma unroll
            for (int ntl = 0; ntl < 9; ntl++) {
                const int nt = nh*9 + ntl;
                const int c = nt*8 + (lane & 3)*2;
                ull a01 = 0ull, a11 = 0ull;
#pragma unroll
                for (int t = 0; t < INH; t++) {
                    const ull wab = *(const ull*)&W[t*GH + c];
                    fma2(a01, o0d[t], wab);
                    fma2(a11, o1d[t], wab);
                }
                *(ull*)&s->h[rr*HS2 + cb + nt*8]     = a01;
                *(ull*)&s->h[(rr+8)*HS2 + cb + nt*8] = a11;
            }
        }
    }
    mix<false>(s);              // L0 mix -> sX (X1 frags)

    if (nh == 0) gemm<0,4>(s, sl, 0 + sl);   // layer 1
    else         gemm<4,5>(s, sl, 0 + sl);
    mix<false>(s);              // -> sX (X2 frags)

    if (nh == 0) gemm<0,4>(s, sl, 2 + sl);   // layer 2
    else         gemm<4,5>(s, sl, 2 + sl);
    mix<true>(s);               // -> gsum (pool . v)

    if (tid < GPC) {
        const int b = cta*GPC + tid;
        out[b] = s->gsum[tid] / nv[b];
    }
}

// ================= launch ======================================================
extern "C" void kernel_launch(void* const* d_in, const int* in_sizes, int n_in,
                              void* d_out, int out_size) {
    const float* ops  = (const float*)d_in[0];
    const float* adj  = (const float*)d_in[1];
    const float* nv   = (const float*)d_in[2];
    const float* w1_0 = (const float*)d_in[3];
    const float* w2_0 = (const float*)d_in[4];
    const float* w1_1 = (const float*)d_in[5];
    const float* w2_1 = (const float*)d_in[6];
    const float* w1_2 = (const float*)d_in[7];
    const float* w2_2 = (const float*)d_in[8];
    const float* fc1  = (const float*)d_in[9];
    const float* fc2  = (const float*)d_in[10];
    float* out = (float*)d_out;

    static int configured = 0;
    if (!configured) {
        cudaFuncSetAttribute(k_fused, cudaFuncAttributeMaxDynamicSharedMemorySize, SMEMB);
        configured = 1;
    }

    k_prep <<<5, 256>>>(w1_1, w2_1, w1_2, w2_2, fc1, fc2);
    k_fused<<<NCTA, NTHR, SMEMB>>>(ops, adj, nv, w1_0, w2_0, out);
}

// round 17
// speedup vs baseline: 1.0469x; 1.0469x over previous
#include <cuda_runtime.h>
#include <cuda_fp16.h>
#include <cstdint>

// ---------------- problem constants ----------------
#define NB     65536
#define GS     7
#define INH    5
#define GH     144
#define LINH   128
#define GPC    4              // graphs per CTA (padded to 8 rows each)
#define NCTA   (NB/GPC)       // 16384
#define NTHR   128            // 4 warps: (nh 0..1) x (sl 0..1)
#define KT     9              // 144/16 k-tiles
#define NT     18             // 144/8 n-tiles
#define NTP    9              // nt-pairs
#define HSH    328            // h row stride in halves; (HSH/2)%32==4 -> conflict-free stores
#define ADJS   56             // padded adjacency stride per graph: 7 rows x 8
#define BSLOT  (KT*NT*256)    // 41472 bytes per weight slot

// ---------------- device scratch ----------------
__device__ unsigned char g_B[4*BSLOT];   // frag-packed fp16 weights (paired-nt uint4)
__device__ float g_v[GH];                // fused fc vector

// ---------------- helpers ----------------
__device__ __forceinline__ uint32_t pack_h(float a, float b) {
    __half2 t = __floats2half2_rn(a, b);   // a in low half
    return *(uint32_t*)&t;
}
// load 4 consecutive halves -> float4 (one LDS.64)
__device__ __forceinline__ float4 ldh4(const __half* p) {
    const uint2 u = *(const uint2*)p;
    const float2 a = __half22float2(*reinterpret_cast<const __half2*>(&u.x));
    const float2 b = __half22float2(*reinterpret_cast<const __half2*>(&u.y));
    return make_float4(a.x, a.y, b.x, b.y);
}
__device__ __forceinline__ void mma_f16(float* c, uint32_t a0, uint32_t a1,
                                        uint32_t a2, uint32_t a3,
                                        uint32_t b0, uint32_t b1) {
    asm volatile(
        "mma.sync.aligned.m16n8k16.row.col.f32.f16.f16.f32 "
        "{%0,%1,%2,%3}, {%4,%5,%6,%7}, {%8,%9}, {%0,%1,%2,%3};"
        : "+f"(c[0]), "+f"(c[1]), "+f"(c[2]), "+f"(c[3])
        : "r"(a0), "r"(a1), "r"(a2), "r"(a3), "r"(b0), "r"(b1));
}

// ---------------- shared memory ----------------
struct SM {
    union {
        uint4 sX[2*KT*32];      // 9216 B: frag-packed fp16 X (2 mtiles)
        struct { float ops[GPC*35]; float w0[2*720]; } l0;
    } u;
    __half h[32*HSH];           // 20992 B: 32 rows x [h1(144) | h2(144)] fp16
    float adjn[GPC*ADJS];       // padded [g][7][8], col 7 = 0
    float adji[GPC*ADJS];
    float adjraw[GPC*49];
    float v[GH];
    float gsum[GPC];
};
#define SMEMB ((int)sizeof(SM))   // ~33.4 KB

// ================= prep kernel: blocks 0-3 pack B, block 4 builds v ===========
// slot order: 0=w1_1 1=w2_1 2=w1_2 3=w2_2.
// B layout: block (kt, ntp) of 512 B; lane l holds [nt=2ntp uint2][nt=2ntp+1 uint2]
__global__ void k_prep(const float* __restrict__ wa, const float* __restrict__ wb,
                       const float* __restrict__ wc, const float* __restrict__ wd,
                       const float* __restrict__ fc1, const float* __restrict__ fc2) {
    if (blockIdx.x == 4) {
        const int k = threadIdx.x;
        if (k < GH) {
            float s = 0.f;
            for (int j = 0; j < LINH; j++) s = fmaf(fc2[j], fc1[j*GH + k], s);
            g_v[k] = s;
        }
        return;
    }
    const float* W = blockIdx.x == 0 ? wa : blockIdx.x == 1 ? wb
                   : blockIdx.x == 2 ? wc : wd;
    unsigned char* out = g_B + (size_t)blockIdx.x * BSLOT;
    for (int f = threadIdx.x; f < KT*NT*32; f += 256) {
        const int kt = f / (NT*32);
        const int nt = (f / 32) % NT;
        const int l  = f & 31;
        const int n  = nt*8 + (l >> 2);
        const int kb = kt*16 + (l & 3)*2;
        uint2 v;
        v.x = pack_h(W[(kb+0)*GH + n], W[(kb+1)*GH + n]);
        v.y = pack_h(W[(kb+8)*GH + n], W[(kb+9)*GH + n]);
        *(uint2*)(out + (size_t)(kt*NTP + (nt >> 1))*512 + l*16 + (nt & 1)*8) = v;
    }
}

// ================= per-graph adjacency prep (padded stride-8 output) ==========
__device__ void prep_graph(SM* s, int g) {
    float a[49];
#pragma unroll
    for (int i = 0; i < 49; i++) a[i] = s->adjraw[g*49 + i];
#pragma unroll
    for (int i = 0; i < 7; i++) {
        a[i*7 + i] += 1.0f;
        float rs = 0.f;
#pragma unroll
        for (int j = 0; j < 7; j++) rs += a[i*7 + j];
        const float inv = 1.0f / rs;
#pragma unroll
        for (int j = 0; j < 7; j++) a[i*7 + j] *= inv;
    }
#pragma unroll
    for (int i = 0; i < 7; i++) {
        float rs = 0.f;
#pragma unroll
        for (int j = 0; j < 7; j++) rs += a[i*7 + j];
        const float inv = 1.0f / rs;
#pragma unroll
        for (int j = 0; j < 7; j++) s->adjn[g*ADJS + i*8 + j] = a[i*7 + j] * inv;
        s->adjn[g*ADJS + i*8 + 7] = 0.f;
    }
#pragma unroll
    for (int i = 0; i < 7; i++) {
        float cs = 0.f;
#pragma unroll
        for (int r = 0; r < 7; r++) cs += a[r*7 + i];
        const float inv = 1.0f / cs;
#pragma unroll
        for (int j = 0; j < 7; j++) s->adji[g*ADJS + i*8 + j] = a[j*7 + i] * inv;
        s->adji[g*ADJS + i*8 + 7] = 0.f;
    }
}

// ================= mix: sH(fp16) -> (sX frags | pooled gsum), 4 cols per item ==
template <bool FINAL>
__device__ void mix(SM* s) {
    const int tid = threadIdx.x;
    __syncthreads();   // sH complete; prior sX reads done

    for (int item = tid; item < GPC*36; item += NTHR) {
        const int g  = item / 36;
        const int kq = item - g*36;
        const int k0 = kq*4;

        float4 h1[7], h2[7];
#pragma unroll
        for (int j = 0; j < 7; j++) {
            h1[j] = ldh4(&s->h[(g*8+j)*HSH + k0]);
            h2[j] = ldh4(&s->h[(g*8+j)*HSH + GH + k0]);
        }
        const float4* an4 = (const float4*)&s->adjn[g*ADJS];
        const float4* ai4 = (const float4*)&s->adji[g*ADJS];

        const int mt = g >> 1;
        const int kt = kq >> 2;
        const int c20 = (kq & 3)*2;
        uint32_t* X = (uint32_t*)s->u.sX;
        const int base  = (mt*KT + kt)*128;
        const int wsel  = (g & 1) + 2*(c20 >> 2);
        const int lbase = c20 & 3;             // 0 or 2

        float cs0 = 0.f, cs1 = 0.f, cs2 = 0.f, cs3 = 0.f;
#pragma unroll
        for (int i = 0; i < 7; i++) {
            float wn[8], wi[8];
            *(float4*)&wn[0] = an4[2*i];  *(float4*)&wn[4] = an4[2*i + 1];
            *(float4*)&wi[0] = ai4[2*i];  *(float4*)&wi[4] = ai4[2*i + 1];
            float o1a=0.f,o1b=0.f,o1c=0.f,o1d=0.f, o2a=0.f,o2b=0.f,o2c=0.f,o2d=0.f;
#pragma unroll
            for (int j = 0; j < 7; j++) {
                o1a = fmaf(wn[j], h1[j].x, o1a); o1b = fmaf(wn[j], h1[j].y, o1b);
                o1c = fmaf(wn[j], h1[j].z, o1c); o1d = fmaf(wn[j], h1[j].w, o1d);
                o2a = fmaf(wi[j], h2[j].x, o2a); o2b = fmaf(wi[j], h2[j].y, o2b);
                o2c = fmaf(wi[j], h2[j].z, o2c); o2d = fmaf(wi[j], h2[j].w, o2d);
            }
            const float x0 = 0.5f * (fmaxf(o1a, 0.f) + fmaxf(o2a, 0.f));
            const float x1 = 0.5f * (fmaxf(o1b, 0.f) + fmaxf(o2b, 0.f));
            const float x2 = 0.5f * (fmaxf(o1c, 0.f) + fmaxf(o2c, 0.f));
            const float x3 = 0.5f * (fmaxf(o1d, 0.f) + fmaxf(o2d, 0.f));

            if (!FINAL) {
                const int l = i*4 + lbase;
                X[base + l*4 + wsel]       = pack_h(x0, x1);
                X[base + (l+1)*4 + wsel]   = pack_h(x2, x3);
            } else {
                cs0 += x0; cs1 += x1; cs2 += x2; cs3 += x3;
            }
        }
        if (FINAL)
            atomicAdd(&s->gsum[g], cs0*s->v[k0] + cs1*s->v[k0+1]
                                 + cs2*s->v[k0+2] + cs3*s->v[k0+3]);
    }
    __syncthreads();   // sX/gsum complete before next phase
}

// ================= GEMM: both mtiles per warp; B uint4 feeds 4 mma ===========
template <int P0, int PN>
__device__ void gemm(SM* s, int sl, int slot) {
    const int lane = threadIdx.x & 31;
    const uint4* __restrict__ Bp = (const uint4*)(g_B + (size_t)slot*BSLOT);
    const uint4* Xv = s->u.sX;

    float acc[2][2*PN][4];
#pragma unroll
    for (int m = 0; m < 2; m++)
#pragma unroll
        for (int t = 0; t < 2*PN; t++)
#pragma unroll
            for (int q = 0; q < 4; q++) acc[m][t][q] = 0.f;

#pragma unroll 1
    for (int kt = 0; kt < KT; kt++) {
        const uint4 a0 = Xv[kt*32 + lane];
        const uint4 a1 = Xv[(KT + kt)*32 + lane];
#pragma unroll
        for (int p = 0; p < PN; p++) {
            const uint4 b = Bp[(kt*NTP + P0 + p)*32 + lane];
            mma_f16(acc[0][2*p],     a0.x, a0.y, a0.z, a0.w, b.x, b.y);
            mma_f16(acc[0][2*p + 1], a0.x, a0.y, a0.z, a0.w, b.z, b.w);
            mma_f16(acc[1][2*p],     a1.x, a1.y, a1.z, a1.w, b.x, b.y);
            mma_f16(acc[1][2*p + 1], a1.x, a1.y, a1.z, a1.w, b.z, b.w);
        }
    }

    // fp16 h stores: one STS.32 per (row, nt)
    const int c0 = sl*GH + (lane & 3)*2;
#pragma unroll
    for (int m = 0; m < 2; m++) {
        const int r0 = m*16 + (lane >> 2);
#pragma unroll
        for (int p = 0; p < PN; p++) {
#pragma unroll
            for (int q = 0; q < 2; q++) {
                const int nt = 2*(P0 + p) + q;
                *(uint32_t*)&s->h[r0*HSH + c0 + nt*8]     = pack_h(acc[m][2*p+q][0], acc[m][2*p+q][1]);
                *(uint32_t*)&s->h[(r0+8)*HSH + c0 + nt*8] = pack_h(acc[m][2*p+q][2], acc[m][2*p+q][3]);
            }
        }
    }
}

// ================= the fused kernel ===========================================
__global__ void __launch_bounds__(NTHR, 4)
k_fused(const float* __restrict__ ops, const float* __restrict__ adj,
        const float* __restrict__ nv,
        const float* __restrict__ w1_0, const float* __restrict__ w2_0,
        float* __restrict__ out) {
    extern __shared__ unsigned char smraw[];
    SM* s = (SM*)smraw;
    const int cta = blockIdx.x, tid = threadIdx.x;
    const int warp = tid >> 5, lane = tid & 31;
    const int sl = warp & 1, nh = warp >> 1;

    // ---- cooperative loads ----
    for (int q = tid; q < GPC*35; q += NTHR) s->u.l0.ops[q] = ops[(size_t)cta*GPC*35 + q];
    for (int q = tid; q < 720; q += NTHR) {
        s->u.l0.w0[q]       = w1_0[q];
        s->u.l0.w0[720 + q] = w2_0[q];
    }
    for (int q = tid; q < GH; q += NTHR)     s->v[q] = g_v[q];
    for (int q = tid; q < GPC*49; q += NTHR) s->adjraw[q] = adj[(size_t)cta*GPC*49 + q];
    if (tid < GPC) s->gsum[tid] = 0.f;
    __syncthreads();

    // ---- adjacency prep (one thread per graph) ----
    if (tid < GPC) prep_graph(s, tid);

    // ---- layer 0: h = ops @ W (K=5); warp covers (sl, nt in [nh*9, nh*9+9)), both mt
    {
        const int r0 = lane >> 2;          // 0..7 (7 = pad row)
        const float* W = &s->u.l0.w0[sl*720];
        const int cb = sl*GH + (lane & 3)*2;
#pragma unroll
        for (int m = 0; m < 2; m++) {
            const int g0 = 2*m, g1 = 2*m + 1;
            float o0[INH], o1[INH];
#pragma unroll
            for (int t = 0; t < INH; t++) {
                o0[t] = (r0 < 7) ? s->u.l0.ops[g0*35 + r0*5 + t] : 0.f;
                o1[t] = (r0 < 7) ? s->u.l0.ops[g1*35 + r0*5 + t] : 0.f;
            }
            const int rr = m*16 + r0;
#pragma unroll
            for (int ntl = 0; ntl < 9; ntl++) {
                const int nt = nh*9 + ntl;
                const int c = nt*8 + (lane & 3)*2;
                float h00 = 0.f, h01 = 0.f, h10 = 0.f, h11 = 0.f;
#pragma unroll
                for (int t = 0; t < INH; t++) {
                    const float wa = W[t*GH + c], wb = W[t*GH + c + 1];
                    h00 = fmaf(o0[t], wa, h00); h01 = fmaf(o0[t], wb, h01);
                    h10 = fmaf(o1[t], wa, h10); h11 = fmaf(o1[t], wb, h11);
                }
                *(uint32_t*)&s->h[rr*HSH + cb + nt*8]     = pack_h(h00, h01);
                *(uint32_t*)&s->h[(rr+8)*HSH + cb + nt*8] = pack_h(h10, h11);
            }
        }
    }
    mix<false>(s);              // L0 mix -> sX (X1 frags)

    if (nh == 0) gemm<0,4>(s, sl, 0 + sl);   // layer 1
    else         gemm<4,5>(s, sl, 0 + sl);
    mix<false>(s);              // -> sX (X2 frags)

    if (nh == 0) gemm<0,4>(s, sl, 2 + sl);   // layer 2
    else         gemm<4,5>(s, sl, 2 + sl);
    mix<true>(s);               // -> gsum (pool . v)

    if (tid < GPC) {
        const int b = cta*GPC + tid;
        out[b] = s->gsum[tid] / nv[b];
    }
}

// ================= launch ======================================================
extern "C" void kernel_launch(void* const* d_in, const int* in_sizes, int n_in,
                              void* d_out, int out_size) {
    const float* ops  = (const float*)d_in[0];
    const float* adj  = (const float*)d_in[1];
    const float* nv   = (const float*)d_in[2];
    const float* w1_0 = (const float*)d_in[3];
    const float* w2_0 = (const float*)d_in[4];
    const float* w1_1 = (const float*)d_in[5];
    const float* w2_1 = (const float*)d_in[6];
    const float* w1_2 = (const float*)d_in[7];
    const float* w2_2 = (const float*)d_in[8];
    const float* fc1  = (const float*)d_in[9];
    const float* fc2  = (const float*)d_in[10];
    float* out = (float*)d_out;

    static int configured = 0;
    if (!configured) {
        cudaFuncSetAttribute(k_fused, cudaFuncAttributeMaxDynamicSharedMemorySize, SMEMB);
        configured = 1;
    }

    k_prep <<<5, 256>>>(w1_1, w2_1, w1_2, w2_2, fc1, fc2);
    k_fused<<<NCTA, NTHR, SMEMB>>>(ops, adj, nv, w1_0, w2_0, out);
}